// round 7
// baseline (speedup 1.0000x reference)
#include <cuda_runtime.h>
#include <stdint.h>

// ---------------------------------------------------------------------------
// Persistent fp32 RNN, k-pair packed f32x2 math, register-resident Wh.
//
// out[t] = tanh(x[t] @ Wi^T + h @ Wh^T),  h = out[t]
//
// 8 batch-groups x 16 H-slice CTAs = 128 CTAs, 512 threads (16 warps).
// Critical-path h-part: Wh slice (64 u64) lives in REGISTERS -> inner loop is
// 2 LDS.128 + 16 fma2 per k-pair. x-part (overlapped with producer wait)
// keeps weights in smem. Inter-CTA sync = per-CTA monotonic release flags;
// warp w consumes exactly producer CTA (g,w)'s output slice.
// ---------------------------------------------------------------------------

namespace {
constexpr int kT = 1024, kB = 128, kI = 256, kH = 512;
constexpr int NG = 8, BG = 16, NC = 16, JC = 32;
constexpr int NTHR = 512, NWARP = 16;
constexpr int KP_H = kH / 2;          // 256
constexpr int KP_X = kI / 2;          // 128
constexpr int KPT  = KP_H + KP_X;     // 384
constexpr int XW = KP_X / NWARP;      // 8 x k-pairs per warp
constexpr int HW = KP_H / NWARP;      // 16 h k-pairs per warp

constexpr int WS_STRIDE = 34;         // u64 per weight row
constexpr int HD_STRIDE = 18;         // u64 per Hd row (16 cols + pad)
constexpr int PS_STRIDE = 34;         // floats per Ps row

constexpr int OFF_WS = 0;
constexpr int OFF_HD = KPT * WS_STRIDE;             // u64 units
constexpr int OFF_PS = OFF_HD + KPT * HD_STRIDE;
constexpr int PS_U64 = NWARP * BG * PS_STRIDE / 2;
constexpr int OFF_AUX = OFF_PS + PS_U64;            // 1 u64: flag base
constexpr int SMEM_U64 = OFF_AUX + 1;
constexpr size_t SMEM_BYTES = size_t(SMEM_U64) * 8;
}

__device__ unsigned g_rnn_flag[NG * NC];   // zero-init; monotonic forever

__device__ __forceinline__ void fma2(unsigned long long& acc,
                                     unsigned long long a,
                                     unsigned long long b) {
    asm("fma.rn.f32x2 %0, %1, %2, %0;" : "+l"(acc) : "l"(a), "l"(b));
}

// weights from smem (x-part)
#define STEP16S(wp, hp)                                                      \
    do {                                                                     \
        const ulonglong2 w0 = *reinterpret_cast<const ulonglong2*>(wp);      \
        const ulonglong2 w1 = *reinterpret_cast<const ulonglong2*>((wp)+16); \
        const ulonglong2 h0 = *reinterpret_cast<const ulonglong2*>(hp);      \
        const ulonglong2 h1 = *reinterpret_cast<const ulonglong2*>((hp)+2);  \
        fma2(acc[0],  w0.x, h0.x); fma2(acc[4],  w0.y, h0.x);                \
        fma2(acc[8],  w1.x, h0.x); fma2(acc[12], w1.y, h0.x);                \
        fma2(acc[1],  w0.x, h0.y); fma2(acc[5],  w0.y, h0.y);                \
        fma2(acc[9],  w1.x, h0.y); fma2(acc[13], w1.y, h0.y);                \
        fma2(acc[2],  w0.x, h1.x); fma2(acc[6],  w0.y, h1.x);                \
        fma2(acc[10], w1.x, h1.x); fma2(acc[14], w1.y, h1.x);                \
        fma2(acc[3],  w0.x, h1.y); fma2(acc[7],  w0.y, h1.y);                \
        fma2(acc[11], w1.x, h1.y); fma2(acc[15], w1.y, h1.y);                \
    } while (0)

// weights from registers (h-part): wr = &whr[4*i]
#define STEP16R(wr, hp)                                                      \
    do {                                                                     \
        const ulonglong2 h0 = *reinterpret_cast<const ulonglong2*>(hp);      \
        const ulonglong2 h1 = *reinterpret_cast<const ulonglong2*>((hp)+2);  \
        fma2(acc[0],  (wr)[0], h0.x); fma2(acc[4],  (wr)[1], h0.x);          \
        fma2(acc[8],  (wr)[2], h0.x); fma2(acc[12], (wr)[3], h0.x);          \
        fma2(acc[1],  (wr)[0], h0.y); fma2(acc[5],  (wr)[1], h0.y);          \
        fma2(acc[9],  (wr)[2], h0.y); fma2(acc[13], (wr)[3], h0.y);          \
        fma2(acc[2],  (wr)[0], h1.x); fma2(acc[6],  (wr)[1], h1.x);          \
        fma2(acc[10], (wr)[2], h1.x); fma2(acc[14], (wr)[3], h1.x);          \
        fma2(acc[3],  (wr)[0], h1.y); fma2(acc[7],  (wr)[1], h1.y);          \
        fma2(acc[11], (wr)[2], h1.y); fma2(acc[15], (wr)[3], h1.y);          \
    } while (0)

__global__ void __launch_bounds__(NTHR, 1)
rnn_wreg_kernel(const float* __restrict__ x,
                const float* __restrict__ Wi,
                const float* __restrict__ Wh,
                float* __restrict__ out,
                int write_tail)
{
    extern __shared__ unsigned long long smu[];
    unsigned long long* Ws = smu + OFF_WS;
    unsigned long long* Hd = smu + OFF_HD;
    float*              Ps = reinterpret_cast<float*>(smu + OFF_PS);
    unsigned*           Aux = reinterpret_cast<unsigned*>(smu + OFF_AUX);

    const int tid = threadIdx.x;
    const int g   = blockIdx.x >> 4;
    const int c   = blockIdx.x & 15;
    const int bg0 = g * BG;
    const int jg0 = c * JC;

    // ---- prologue ----------------------------------------------------------
    if (tid == 0) Aux[0] = g_rnn_flag[blockIdx.x];   // own flag == all flags

    {   // weights, column-permuted
        const int jl  = tid >> 4;
        const int kpb = tid & 15;
        const int dst = (jl >> 2) * 2 + ((jl >> 1) & 1) * 16 + (jl & 1);
        const float2* whp = reinterpret_cast<const float2*>(
            Wh + (size_t)(jg0 + jl) * kH);
        #pragma unroll
        for (int i = 0; i < KP_H / 16; ++i) {
            int kp = kpb + 16 * i;
            float2 v = __ldg(whp + kp);
            Ws[kp * WS_STRIDE + dst] = *reinterpret_cast<unsigned long long*>(&v);
        }
        const float2* wip = reinterpret_cast<const float2*>(
            Wi + (size_t)(jg0 + jl) * kI);
        #pragma unroll
        for (int i = 0; i < KP_X / 16; ++i) {
            int kp = kpb + 16 * i;
            float2 v = __ldg(wip + kp);
            Ws[(KP_H + kp) * WS_STRIDE + dst] =
                *reinterpret_cast<unsigned long long*>(&v);
        }
    }
    for (int e = tid; e < KP_H * HD_STRIDE; e += NTHR) Hd[e] = 0ull;
    {   // x[0]
        const int b = tid >> 5, l = tid & 31;
        const int col = b ^ (4 * ((l >> 3) & 3));
        const float2* xp = reinterpret_cast<const float2*>(
            x + (size_t)(bg0 + b) * kI);
        #pragma unroll
        for (int i = 0; i < 4; ++i) {
            float2 v = __ldcg(xp + l + 32 * i);
            Hd[(KP_H + l + 32 * i) * HD_STRIDE + col] =
                *reinterpret_cast<unsigned long long*>(&v);
        }
    }
    __syncthreads();
    const unsigned base = Aux[0];

    // ---- per-thread geometry ------------------------------------------------
    const int w    = tid >> 5;
    const int lane = tid & 31;
    const int jq   = lane & 7;
    const int bp   = lane >> 3;
    const int rb   = w, rl = lane;
    const int wrcol = rb ^ (4 * ((rl >> 3) & 3));

    volatile unsigned* flagp = g_rnn_flag + (g * NC + w);
    unsigned* myflag = g_rnn_flag + blockIdx.x;

    // readback geometry (warp w <- producer CTA (g,w), j in [32w,32w+32))
    const int p    = lane & 15;
    const int bh   = (lane >> 4) * 8;
    const int pge8 = (p >> 3) & 1;
    const int hswz = 4 * ((2 * w + pge8) & 3);

    const unsigned long long* wx  = Ws + (size_t)(KP_H + XW * w) * WS_STRIDE + jq * 2;
    const unsigned long long* hx  = Hd + (size_t)(KP_H + XW * w) * HD_STRIDE
                                       + 4 * (bp ^ (w & 3));
    const unsigned long long* wh0 = Ws + (size_t)(HW * w) * WS_STRIDE + jq * 2;
    const unsigned long long* hh0 = Hd + (size_t)(HW * w) * HD_STRIDE
                                       + 4 * (bp ^ ((2 * w) & 3));
    const unsigned long long* hh1 = Hd + (size_t)(HW * w + 8) * HD_STRIDE
                                       + 4 * (bp ^ ((2 * w + 1) & 3));

    // ---- hoist h-part weight slice into registers (stationary) --------------
    unsigned long long whr[4 * HW];   // 64 u64 = 128 regs
    #pragma unroll
    for (int i = 0; i < HW; ++i) {
        const unsigned long long* wp = wh0 + (size_t)i * WS_STRIDE;
        const ulonglong2 a = *reinterpret_cast<const ulonglong2*>(wp);
        const ulonglong2 b = *reinterpret_cast<const ulonglong2*>(wp + 16);
        whr[4 * i + 0] = a.x;  whr[4 * i + 1] = a.y;
        whr[4 * i + 2] = b.x;  whr[4 * i + 3] = b.y;
    }

    unsigned long long acc[16];

    // ---- x-part for t=0 ------------------------------------------------------
    {
        #pragma unroll
        for (int i = 0; i < 16; ++i) acc[i] = 0ull;
        const unsigned long long* wp = wx;
        const unsigned long long* hp = hx;
        #pragma unroll
        for (int i = 0; i < XW; ++i) { STEP16S(wp, hp); wp += WS_STRIDE; hp += HD_STRIDE; }
    }

    for (int t = 0; t < kT; ++t) {
        // ---- h-part: register weights, 2 LDS.128 per k-pair -------------------
        {
            const unsigned long long* hp = hh0;
            #pragma unroll
            for (int i = 0; i < 8; ++i) { STEP16R(whr + 4 * i, hp); hp += HD_STRIDE; }
            hp = hh1;
            #pragma unroll
            for (int i = 8; i < 16; ++i) { STEP16R(whr + 4 * i, hp); hp += HD_STRIDE; }
        }

        // ---- scatter partials (conflict-free) --------------------------------
        #pragma unroll
        for (int bb = 0; bb < 4; ++bb) {
            const int row = (w * BG + 4 * bp + bb) * PS_STRIDE;
            #pragma unroll
            for (int jj = 0; jj < 4; ++jj) {
                float2 f = *reinterpret_cast<float2*>(&acc[jj * 4 + bb]);
                Ps[row + jj * 8 + jq] = f.x + f.y;
            }
        }

        // ---- prefetch x[t+1] ---------------------------------------------------
        float2 xr[4];
        if (t + 1 < kT) {
            const float2* xp = reinterpret_cast<const float2*>(
                x + (size_t)(t + 1) * kB * kI + (size_t)(bg0 + rb) * kI);
            #pragma unroll
            for (int i = 0; i < 4; ++i) xr[i] = __ldcg(xp + rl + 32 * i);
        }
        __syncthreads();                                   // S1: Ps ready

        // ---- reduce, tanh, store out[t] ---------------------------------------
        {
            const int cf = (rl & 3) * 8 + (rl >> 2);
            float pv[16];
            #pragma unroll
            for (int ws = 0; ws < NWARP; ++ws)
                pv[ws] = Ps[(ws * BG + rb) * PS_STRIDE + cf];
            #pragma unroll
            for (int s = 8; s >= 1; s >>= 1)
                #pragma unroll
                for (int i = 0; i < s; ++i) pv[i] += pv[i + s];
            float r = tanhf(pv[0]);
            size_t o = (size_t)t * kB * kH + (size_t)(bg0 + rb) * kH + jg0 + rl;
            out[o] = r;
            if (t == kT - 1 && write_tail)
                out[(size_t)kT * kB * kH + (size_t)(bg0 + rb) * kH + jg0 + rl] = r;
        }
        if (t + 1 == kT) break;

        // ---- stage x[t+1] ------------------------------------------------------
        #pragma unroll
        for (int i = 0; i < 4; ++i)
            Hd[(KP_H + rl + 32 * i) * HD_STRIDE + wrcol] =
                *reinterpret_cast<unsigned long long*>(&xr[i]);

        __syncthreads();                                   // S2: STG + x staged

        if (tid == 0) {                                    // release out[t]
            asm volatile("red.release.gpu.global.add.u32 [%0], %1;"
                         :: "l"(myflag), "r"(1u) : "memory");
        }

        // ---- x-part(t+1): overlaps producer wait (smem weights) ---------------
        {
            #pragma unroll
            for (int i = 0; i < 16; ++i) acc[i] = 0ull;
            const unsigned long long* wp = wx;
            const unsigned long long* hp = hx;
            #pragma unroll
            for (int i = 0; i < XW; ++i) { STEP16S(wp, hp); wp += WS_STRIDE; hp += HD_STRIDE; }
        }

        // ---- wait single producer, read its h slice, stage (warp-private) -----
        {
            const unsigned target = base + (unsigned)(t + 1);
            unsigned cur;
            do {
                asm volatile("ld.acquire.gpu.global.u32 %0, [%1];"
                             : "=r"(cur) : "l"((const unsigned*)flagp) : "memory");
            } while ((int)(cur - target) < 0);

            const float* hb = out + (size_t)t * kB * kH + (size_t)bg0 * kH
                                  + 32 * w + 2 * p;
            float2 hv[8];
            #pragma unroll
            for (int i = 0; i < 8; ++i) {
                const int brd = ((((2 * i) & 6) | (i >> 2)) ^ pge8);
                hv[i] = __ldcg(reinterpret_cast<const float2*>(
                    hb + (size_t)(bh + brd) * kH));
            }
            #pragma unroll
            for (int i = 0; i < 8; ++i) {
                const int brd = ((((2 * i) & 6) | (i >> 2)) ^ pge8);
                Hd[(16 * w + p) * HD_STRIDE + ((bh + brd) ^ hswz)] =
                    *reinterpret_cast<unsigned long long*>(&hv[i]);
            }
            __syncwarp();
        }
    }
}

extern "C" void kernel_launch(void* const* d_in, const int* in_sizes, int n_in,
                              void* d_out, int out_size) {
    const float* x  = (const float*)d_in[0];   // [T,B,I]
    const float* Wi = (const float*)d_in[1];   // [H,I]
    const float* Wh = (const float*)d_in[2];   // [H,H]
    float* out = (float*)d_out;

    const long long main_elems = (long long)kT * kB * kH;
    int write_tail = ((long long)out_size >= main_elems + (long long)kB * kH) ? 1 : 0;

    cudaFuncSetAttribute(rnn_wreg_kernel,
                         cudaFuncAttributeMaxDynamicSharedMemorySize,
                         (int)SMEM_BYTES);
    rnn_wreg_kernel<<<NG * NC, NTHR, SMEM_BYTES>>>(x, Wi, Wh, out, write_tail);
}

// round 8
// speedup vs baseline: 1.7833x; 1.7833x over previous
#include <cuda_runtime.h>
#include <stdint.h>

// ---------------------------------------------------------------------------
// Persistent fp32 RNN, k-pair packed f32x2, half-register-resident Wh.
//
// out[t] = tanh(x[t] @ Wi^T + h @ Wh^T),  h = out[t]
//
// 8 batch-groups x 16 H-slice CTAs = 128 CTAs, 256 threads (8 warps).
// 256 thr/CTA => 255 regs/thread budget. Warp w owns h k-pairs [32w,32w+32)
// (first 16 kp: weights in 128 REGISTERS; last 16 kp: weights from smem)
// and x k-pairs [16w,16w+16) (smem weights, overlapped with producer wait).
// Warp w consumes producer CTAs (g,2w) and (g,2w+1); per-CTA monotonic flags.
// ---------------------------------------------------------------------------

namespace {
constexpr int kT = 1024, kB = 128, kI = 256, kH = 512;
constexpr int NG = 8, BG = 16, NC = 16, JC = 32;
constexpr int NTHR = 256, NWARP = 8;
constexpr int KP_H = kH / 2;          // 256
constexpr int KP_X = kI / 2;          // 128
constexpr int KPT  = KP_H + KP_X;     // 384
constexpr int XW = KP_X / NWARP;      // 16 x k-pairs per warp
constexpr int HWR = 16;               // h k-pairs with register weights
constexpr int HWS = 16;               // h k-pairs with smem weights

constexpr int WS_STRIDE = 34;         // u64 per weight row
constexpr int HD_STRIDE = 18;         // u64 per Hd row
constexpr int PS_STRIDE = 34;         // floats per Ps row

constexpr int OFF_WS = 0;
constexpr int OFF_HD = KPT * WS_STRIDE;             // 13056 u64
constexpr int OFF_PS = OFF_HD + KPT * HD_STRIDE;    // 19968
constexpr int PS_U64 = NWARP * BG * PS_STRIDE / 2;  // 2176
constexpr int OFF_AUX = OFF_PS + PS_U64;
constexpr int SMEM_U64 = OFF_AUX + 1;
constexpr size_t SMEM_BYTES = size_t(SMEM_U64) * 8; // ~177 KB
}

__device__ unsigned g_rnn_flag[NG * NC];   // zero-init; monotonic forever

__device__ __forceinline__ void fma2(unsigned long long& acc,
                                     unsigned long long a,
                                     unsigned long long b) {
    asm("fma.rn.f32x2 %0, %1, %2, %0;" : "+l"(acc) : "l"(a), "l"(b));
}

// weights from smem
#define STEP16S(wp, hp)                                                      \
    do {                                                                     \
        const ulonglong2 w0 = *reinterpret_cast<const ulonglong2*>(wp);      \
        const ulonglong2 w1 = *reinterpret_cast<const ulonglong2*>((wp)+16); \
        const ulonglong2 h0 = *reinterpret_cast<const ulonglong2*>(hp);      \
        const ulonglong2 h1 = *reinterpret_cast<const ulonglong2*>((hp)+2);  \
        fma2(acc[0],  w0.x, h0.x); fma2(acc[4],  w0.y, h0.x);                \
        fma2(acc[8],  w1.x, h0.x); fma2(acc[12], w1.y, h0.x);                \
        fma2(acc[1],  w0.x, h0.y); fma2(acc[5],  w0.y, h0.y);                \
        fma2(acc[9],  w1.x, h0.y); fma2(acc[13], w1.y, h0.y);                \
        fma2(acc[2],  w0.x, h1.x); fma2(acc[6],  w0.y, h1.x);                \
        fma2(acc[10], w1.x, h1.x); fma2(acc[14], w1.y, h1.x);                \
        fma2(acc[3],  w0.x, h1.y); fma2(acc[7],  w0.y, h1.y);                \
        fma2(acc[11], w1.x, h1.y); fma2(acc[15], w1.y, h1.y);                \
    } while (0)

// weights from registers: wr = &whr[4*i]
#define STEP16R(wr, hp)                                                      \
    do {                                                                     \
        const ulonglong2 h0 = *reinterpret_cast<const ulonglong2*>(hp);      \
        const ulonglong2 h1 = *reinterpret_cast<const ulonglong2*>((hp)+2);  \
        fma2(acc[0],  (wr)[0], h0.x); fma2(acc[4],  (wr)[1], h0.x);          \
        fma2(acc[8],  (wr)[2], h0.x); fma2(acc[12], (wr)[3], h0.x);          \
        fma2(acc[1],  (wr)[0], h0.y); fma2(acc[5],  (wr)[1], h0.y);          \
        fma2(acc[9],  (wr)[2], h0.y); fma2(acc[13], (wr)[3], h0.y);          \
        fma2(acc[2],  (wr)[0], h1.x); fma2(acc[6],  (wr)[1], h1.x);          \
        fma2(acc[10], (wr)[2], h1.x); fma2(acc[14], (wr)[3], h1.x);          \
        fma2(acc[3],  (wr)[0], h1.y); fma2(acc[7],  (wr)[1], h1.y);          \
        fma2(acc[11], (wr)[2], h1.y); fma2(acc[15], (wr)[3], h1.y);          \
    } while (0)

__global__ void __launch_bounds__(NTHR, 1)
rnn_wreg256_kernel(const float* __restrict__ x,
                   const float* __restrict__ Wi,
                   const float* __restrict__ Wh,
                   float* __restrict__ out,
                   int write_tail)
{
    extern __shared__ unsigned long long smu[];
    unsigned long long* Ws = smu + OFF_WS;
    unsigned long long* Hd = smu + OFF_HD;
    float*              Ps = reinterpret_cast<float*>(smu + OFF_PS);
    unsigned*           Aux = reinterpret_cast<unsigned*>(smu + OFF_AUX);

    const int tid = threadIdx.x;
    const int g   = blockIdx.x >> 4;
    const int c   = blockIdx.x & 15;
    const int bg0 = g * BG;
    const int jg0 = c * JC;

    // ---- prologue ----------------------------------------------------------
    if (tid == 0) Aux[0] = g_rnn_flag[blockIdx.x];

    {   // weights, column-permuted: dst(j) = (j>>2)*2 + ((j>>1)&1)*16 + (j&1)
        const int jl  = tid >> 3;                  // 0..31
        const int kpb = tid & 7;                   // 0..7
        const int dst = (jl >> 2) * 2 + ((jl >> 1) & 1) * 16 + (jl & 1);
        const float2* whp = reinterpret_cast<const float2*>(
            Wh + (size_t)(jg0 + jl) * kH);
        #pragma unroll
        for (int i = 0; i < KP_H / 8; ++i) {
            int kp = kpb + 8 * i;
            float2 v = __ldg(whp + kp);
            Ws[kp * WS_STRIDE + dst] = *reinterpret_cast<unsigned long long*>(&v);
        }
        const float2* wip = reinterpret_cast<const float2*>(
            Wi + (size_t)(jg0 + jl) * kI);
        #pragma unroll
        for (int i = 0; i < KP_X / 8; ++i) {
            int kp = kpb + 8 * i;
            float2 v = __ldg(wip + kp);
            Ws[(KP_H + kp) * WS_STRIDE + dst] =
                *reinterpret_cast<unsigned long long*>(&v);
        }
    }
    for (int e = tid; e < KP_H * HD_STRIDE; e += NTHR) Hd[e] = 0ull;
    __syncthreads();
    const unsigned base = Aux[0];

    // ---- per-thread geometry ------------------------------------------------
    const int w    = tid >> 5;           // warp 0..7
    const int lane = tid & 31;
    const int jq   = lane & 7;
    const int bp   = lane >> 3;

    // x staging role: batch bx = 2w + (lane>>4), k-pair lane rl16
    const int bx   = 2 * w + (lane >> 4);
    const int rl16 = lane & 15;

    // h readback role (per producer q in {0,1}; producer CTA = 2w+q)
    const int p    = lane & 15;
    const int bh   = (lane >> 4) * 8;
    const int pge8 = (p >> 3) & 1;

    // stage x[0]
    {
        const float2* xp = reinterpret_cast<const float2*>(
            x + (size_t)(bg0 + bx) * kI);
        #pragma unroll
        for (int i = 0; i < 8; ++i) {
            int kp = rl16 + 16 * i;
            float2 v = __ldcg(xp + kp);
            int col = bx ^ (4 * (((rl16 >> 3) + 2 * i) & 3));
            Hd[(KP_H + kp) * HD_STRIDE + col] =
                *reinterpret_cast<unsigned long long*>(&v);
        }
    }

    // ---- pointers ------------------------------------------------------------
    const unsigned long long* wx  = Ws + (size_t)(KP_H + XW * w) * WS_STRIDE + jq * 2;
    const unsigned long long* hx0 = Hd + (size_t)(KP_H + XW * w) * HD_STRIDE
                                       + 4 * (bp ^ ((2 * w) & 3));
    const unsigned long long* hx1 = Hd + (size_t)(KP_H + XW * w + 8) * HD_STRIDE
                                       + 4 * (bp ^ ((2 * w + 1) & 3));

    const unsigned long long* whA = Ws + (size_t)(32 * w) * WS_STRIDE + jq * 2;       // reg src
    const unsigned long long* whB = Ws + (size_t)(32 * w + 16) * WS_STRIDE + jq * 2;  // smem
    const unsigned long long* hh0 = Hd + (size_t)(32 * w) * HD_STRIDE      + 4 * (bp ^ 0);
    const unsigned long long* hh1 = Hd + (size_t)(32 * w + 8) * HD_STRIDE  + 4 * (bp ^ 1);
    const unsigned long long* hh2 = Hd + (size_t)(32 * w + 16) * HD_STRIDE + 4 * (bp ^ 2);
    const unsigned long long* hh3 = Hd + (size_t)(32 * w + 24) * HD_STRIDE + 4 * (bp ^ 3);

    // ---- hoist first 16 h k-pairs' weights into registers ---------------------
    unsigned long long whr[4 * HWR];   // 64 u64 = 128 regs
    #pragma unroll
    for (int i = 0; i < HWR; ++i) {
        const unsigned long long* wp = whA + (size_t)i * WS_STRIDE;
        const ulonglong2 a = *reinterpret_cast<const ulonglong2*>(wp);
        const ulonglong2 b = *reinterpret_cast<const ulonglong2*>(wp + 16);
        whr[4 * i + 0] = a.x;  whr[4 * i + 1] = a.y;
        whr[4 * i + 2] = b.x;  whr[4 * i + 3] = b.y;
    }
    __syncthreads();   // x[0] staged

    unsigned long long acc[16];

    // ---- x-part for t=0 --------------------------------------------------------
    {
        #pragma unroll
        for (int i = 0; i < 16; ++i) acc[i] = 0ull;
        const unsigned long long* wp = wx;
        const unsigned long long* hp = hx0;
        #pragma unroll
        for (int i = 0; i < 8; ++i) { STEP16S(wp, hp); wp += WS_STRIDE; hp += HD_STRIDE; }
        hp = hx1;
        #pragma unroll
        for (int i = 0; i < 8; ++i) { STEP16S(wp, hp); wp += WS_STRIDE; hp += HD_STRIDE; }
    }

    for (int t = 0; t < kT; ++t) {
        // ---- h-part: 16 kp reg-weights + 16 kp smem-weights --------------------
        {
            const unsigned long long* hp = hh0;
            #pragma unroll
            for (int i = 0; i < 8; ++i)  { STEP16R(whr + 4 * i, hp); hp += HD_STRIDE; }
            hp = hh1;
            #pragma unroll
            for (int i = 8; i < 16; ++i) { STEP16R(whr + 4 * i, hp); hp += HD_STRIDE; }
            const unsigned long long* wp = whB;
            hp = hh2;
            #pragma unroll
            for (int i = 0; i < 8; ++i)  { STEP16S(wp, hp); wp += WS_STRIDE; hp += HD_STRIDE; }
            hp = hh3;
            #pragma unroll
            for (int i = 0; i < 8; ++i)  { STEP16S(wp, hp); wp += WS_STRIDE; hp += HD_STRIDE; }
        }

        // ---- scatter partials (conflict-free) ----------------------------------
        #pragma unroll
        for (int bb = 0; bb < 4; ++bb) {
            const int row = (w * BG + 4 * bp + bb) * PS_STRIDE;
            #pragma unroll
            for (int jj = 0; jj < 4; ++jj) {
                float2 f = *reinterpret_cast<float2*>(&acc[jj * 4 + bb]);
                Ps[row + jj * 8 + jq] = f.x + f.y;
            }
        }

        // ---- prefetch x[t+1] -----------------------------------------------------
        float2 xr[8];
        if (t + 1 < kT) {
            const float2* xp = reinterpret_cast<const float2*>(
                x + (size_t)(t + 1) * kB * kI + (size_t)(bg0 + bx) * kI);
            #pragma unroll
            for (int i = 0; i < 8; ++i) xr[i] = __ldcg(xp + rl16 + 16 * i);
        }
        __syncthreads();                                   // S1: Ps ready

        // ---- reduce 8 partials, tanh, store out[t] -------------------------------
        {
            const int b  = tid >> 4;                       // 0..15
            const int jp = tid & 15;
            const int j0 = 2 * jp, j1 = 2 * jp + 1;
            const int cf0 = (j0 & 3) * 8 + (j0 >> 2);
            const int cf1 = (j1 & 3) * 8 + (j1 >> 2);
            float s0 = 0.f, s1 = 0.f;
            #pragma unroll
            for (int ws = 0; ws < NWARP; ++ws) {
                const int row = (ws * BG + b) * PS_STRIDE;
                s0 += Ps[row + cf0];
                s1 += Ps[row + cf1];
            }
            float2 r;
            r.x = tanhf(s0);
            r.y = tanhf(s1);
            size_t o = (size_t)t * kB * kH + (size_t)(bg0 + b) * kH + jg0 + j0;
            *reinterpret_cast<float2*>(out + o) = r;
            if (t == kT - 1 && write_tail)
                *reinterpret_cast<float2*>(
                    out + (size_t)kT * kB * kH + (size_t)(bg0 + b) * kH + jg0 + j0) = r;
        }
        if (t + 1 == kT) break;

        // ---- stage x[t+1] ----------------------------------------------------------
        #pragma unroll
        for (int i = 0; i < 8; ++i) {
            int kp = rl16 + 16 * i;
            int col = bx ^ (4 * (((rl16 >> 3) + 2 * i) & 3));
            Hd[(KP_H + kp) * HD_STRIDE + col] =
                *reinterpret_cast<unsigned long long*>(&xr[i]);
        }

        __syncthreads();                                   // S2: STG + x staged

        if (tid == 0) {                                    // release out[t]
            asm volatile("red.release.gpu.global.add.u32 [%0], %1;"
                         :: "l"(g_rnn_flag + blockIdx.x), "r"(1u) : "memory");
        }

        // ---- x-part(t+1): overlaps producer wait -----------------------------------
        {
            #pragma unroll
            for (int i = 0; i < 16; ++i) acc[i] = 0ull;
            const unsigned long long* wp = wx;
            const unsigned long long* hp = hx0;
            #pragma unroll
            for (int i = 0; i < 8; ++i) { STEP16S(wp, hp); wp += WS_STRIDE; hp += HD_STRIDE; }
            hp = hx1;
            #pragma unroll
            for (int i = 0; i < 8; ++i) { STEP16S(wp, hp); wp += WS_STRIDE; hp += HD_STRIDE; }
        }

        // ---- wait 2 producers, read h slices, stage (warp-private rows) ------------
        {
            const unsigned target = base + (unsigned)(t + 1);
            #pragma unroll
            for (int q = 0; q < 2; ++q) {
                const int pcta = 2 * w + q;
                const unsigned* fp = g_rnn_flag + (g * NC + pcta);
                unsigned cur;
                do {
                    asm volatile("ld.acquire.gpu.global.u32 %0, [%1];"
                                 : "=r"(cur) : "l"(fp) : "memory");
                } while ((int)(cur - target) < 0);

                const int hswz = 4 * ((2 * q + pge8) & 3);
                const float* hb = out + (size_t)t * kB * kH + (size_t)bg0 * kH
                                      + 32 * pcta + 2 * p;
                float2 hv[8];
                #pragma unroll
                for (int i = 0; i < 8; ++i) {
                    const int brd = ((((2 * i) & 6) | (i >> 2)) ^ pge8);
                    hv[i] = __ldcg(reinterpret_cast<const float2*>(
                        hb + (size_t)(bh + brd) * kH));
                }
                #pragma unroll
                for (int i = 0; i < 8; ++i) {
                    const int brd = ((((2 * i) & 6) | (i >> 2)) ^ pge8);
                    Hd[(16 * pcta + p) * HD_STRIDE + ((bh + brd) ^ hswz)] =
                        *reinterpret_cast<unsigned long long*>(&hv[i]);
                }
            }
            __syncwarp();
        }
    }
}

extern "C" void kernel_launch(void* const* d_in, const int* in_sizes, int n_in,
                              void* d_out, int out_size) {
    const float* x  = (const float*)d_in[0];   // [T,B,I]
    const float* Wi = (const float*)d_in[1];   // [H,I]
    const float* Wh = (const float*)d_in[2];   // [H,H]
    float* out = (float*)d_out;

    const long long main_elems = (long long)kT * kB * kH;
    int write_tail = ((long long)out_size >= main_elems + (long long)kB * kH) ? 1 : 0;

    cudaFuncSetAttribute(rnn_wreg256_kernel,
                         cudaFuncAttributeMaxDynamicSharedMemorySize,
                         (int)SMEM_BYTES);
    rnn_wreg256_kernel<<<NG * NC, NTHR, SMEM_BYTES>>>(x, Wi, Wh, out, write_tail);
}